// round 15
// baseline (speedup 1.0000x reference)
#include <cuda_runtime.h>

#define DIM 256
#define NCOL 16
#define BATCH 65536
#define NBLK 512
#define NSETUP 64
typedef unsigned long long ull;

__device__ float g_Cpart[8][81 * 8];   // per-j-chunk partial C tensors
__device__ float g_C[81 * 8];          // summed C (by setup block #63)
__device__ unsigned g_ticket;          // setup completion ticket (self-resetting)
__device__ unsigned g_ready;           // release flag (self-resetting)
__device__ unsigned g_fin;             // block-exit counter (self-resetting)

__device__ __forceinline__ float2 cmul(float2 a, float2 b) {
    return make_float2(a.x * b.x - a.y * b.y, a.x * b.y + a.y * b.x);
}
__device__ __forceinline__ void ffma2(ull& d, ull a, ull b) {
    asm("fma.rn.f32x2 %0, %1, %2, %0;" : "+l"(d) : "l"(a), "l"(b));
}
__device__ __forceinline__ ull mul2(ull a, ull b) {
    ull r;
    asm("mul.rn.f32x2 %0, %1, %2;" : "=l"(r) : "l"(a), "l"(b));
    return r;
}
__device__ __forceinline__ ull dup2(float p) {
    ull r;
    asm("mov.b64 %0, {%1, %2};" : "=l"(r) : "f"(p), "f"(p));
    return r;
}
__device__ __forceinline__ float2 shfl2(float2 v, int src) {
    float2 r;
    r.x = __shfl_sync(0xffffffffu, v.x, src);
    r.y = __shfl_sync(0xffffffffu, v.y, src);
    return r;
}

// swizzled smem index for M: row j (128 B), column XOR'd by j&15 -> conflict-free
#define SIDX(j, c) (((j) << 4) | ((c) ^ ((j) & 15)))

// ---------------------------------------------------------------------------
// ONE kernel, 512 blocks x 256 threads, all co-resident (4 blk/SM via
// launch_bounds regs cap + 33KB smem; 512 <= 592 capacity -> spin cannot
// deadlock). Blocks 0..63: register sim + BC slice -> g_Cpart; the block
// drawing ticket #63 sums partials into g_C and releases g_ready.
// ALL blocks: sample preamble (ldg + sincos + u-prep) BEFORE the spin so it
// overlaps setup latency; then stage C to smem and contract (lane pair per
// sample: even lane outputs 0-3, odd 4-7; 4-inst inner loop).
// ---------------------------------------------------------------------------
__global__ void __launch_bounds__(256, 4) fused_one(const float* __restrict__ x,
                                                    const float* __restrict__ params,
                                                    float* __restrict__ out) {
    __shared__ __align__(16) char sbuf[DIM * NCOL * 8];   // 32 KB: Ms, later Cs
    __shared__ float2 G[16][4];
    __shared__ float Csh[81];
    __shared__ unsigned s_tick;

    float2* Ms = reinterpret_cast<float2*>(sbuf);
    float*  Cs = reinterpret_cast<float*>(sbuf);

    int t = threadIdx.x;
    int ln = t & 31;
    int w = t >> 5;
    int bid = blockIdx.x;

    // ================= setup role (blocks 0..63) =================
    if (bid < NSETUP) {
        int i = bid & 7;                 // output wire
        int q = bid >> 3;                // j chunk

        if (t < 16) {
            int layer = t >> 3, wi = t & 7;
            const float* p = params + layer * 24 + wi * 3;
            float cx, sx, cy, sy, cz, sz;
            __sincosf(0.5f * p[0], &sx, &cx);
            __sincosf(0.5f * p[1], &sy, &cy);
            __sincosf(0.5f * p[2], &sz, &cz);
            float2 a00 = make_float2( cy * cx,  sy * sx);
            float2 a01 = make_float2(-sy * cx, -cy * sx);
            float2 a10 = make_float2( sy * cx, -cy * sx);
            float2 a11 = make_float2( cy * cx, -sy * sx);
            float2 e0 = make_float2(cz, -sz), e1 = make_float2(cz, sz);
            G[t][0] = cmul(e0, a00);
            G[t][1] = cmul(e0, a01);
            G[t][2] = cmul(e1, a10);
            G[t][3] = cmul(e1, a11);
        }
        if (t < 81) Csh[t] = 0.f;
        __syncthreads();

        // ---- Phase A: register sim (warp w owns columns 2w, 2w+1) ----
        float2 st[2][8];
#pragma unroll
        for (int h = 0; h < 2; ++h)
#pragma unroll
            for (int r = 0; r < 8; ++r)
                st[h][r] = make_float2((r == w && ln == (h << 4)) ? 1.f : 0.f, 0.f);

#pragma unroll
        for (int layer = 0; layer < 2; ++layer) {
#pragma unroll
            for (int wi = 0; wi < 8; ++wi) {
                int g = layer * 8 + wi;
                float2 g00 = G[g][0], g01 = G[g][1], g10 = G[g][2], g11 = G[g][3];
                if (wi < 3) {
                    int rb = 1 << (2 - wi);
#pragma unroll
                    for (int h = 0; h < 2; ++h)
#pragma unroll
                        for (int r = 0; r < 8; ++r) {
                            if (r & rb) continue;
                            int r1 = r | rb;
                            float2 a0 = st[h][r], a1 = st[h][r1];
                            float2 n0, n1;
                            n0.x = g00.x * a0.x - g00.y * a0.y + g01.x * a1.x - g01.y * a1.y;
                            n0.y = g00.x * a0.y + g00.y * a0.x + g01.x * a1.y + g01.y * a1.x;
                            n1.x = g10.x * a0.x - g10.y * a0.y + g11.x * a1.x - g11.y * a1.y;
                            n1.y = g10.x * a0.y + g10.y * a0.x + g11.x * a1.y + g11.y * a1.x;
                            st[h][r] = n0; st[h][r1] = n1;
                        }
                } else {
                    int mk = 1 << (7 - wi);
                    bool hi = (ln & mk) != 0;
                    float2 ga = hi ? g11 : g00;
                    float2 gb = hi ? g10 : g01;
#pragma unroll
                    for (int h = 0; h < 2; ++h)
#pragma unroll
                        for (int r = 0; r < 8; ++r) {
                            float2 m = st[h][r];
                            float2 p;
                            p.x = __shfl_xor_sync(0xffffffffu, m.x, mk);
                            p.y = __shfl_xor_sync(0xffffffffu, m.y, mk);
                            float2 n;
                            n.x = ga.x * m.x - ga.y * m.y + gb.x * p.x - gb.y * p.y;
                            n.y = ga.x * m.y + ga.y * m.x + gb.x * p.y + gb.y * p.x;
                            st[h][r] = n;
                        }
                }
            }
            // CNOT chain: new[j] = old[j ^ (j>>1)]
            int baseLane = (ln ^ (ln >> 1)) & 31;
            float2 tmp[2][8];
#pragma unroll
            for (int h = 0; h < 2; ++h)
#pragma unroll
                for (int r = 0; r < 8; ++r) {
                    int sr = r ^ (r >> 1);
                    int srcLane = baseLane ^ ((r & 1) << 4);
                    tmp[h][r] = shfl2(st[h][sr], srcLane);
                }
#pragma unroll
            for (int h = 0; h < 2; ++h)
#pragma unroll
                for (int r = 0; r < 8; ++r) st[h][r] = tmp[h][r];
        }

#pragma unroll
        for (int h = 0; h < 2; ++h)
#pragma unroll
            for (int r = 0; r < 8; ++r) {
                int j = ln + 32 * r;
                Ms[SIDX(j, 2 * w + h)] = st[h][r];
            }
        __syncthreads();

        // ---- Phase B: BC slice (wire i, j in [32q, 32q+32)) ----
        int k = t >> 4, l = t & 15;
        int shift = 7 - i;
        float ar = 0.f, ai = 0.f;
#pragma unroll
        for (int jj = 0; jj < 32; ++jj) {
            int j = q * 32 + jj;
            float2 mk2 = Ms[SIDX(j, k)];
            float2 ml2 = Ms[SIDX(j, l)];
            float pr = mk2.x * ml2.x + mk2.y * ml2.y;
            float pi = mk2.x * ml2.y - mk2.y * ml2.x;
            float sg = ((j >> shift) & 1) ? -1.f : 1.f;
            ar = fmaf(sg, pr, ar);
            ai = fmaf(sg, pi, ai);
        }
        int d = (__popc(k) - __popc(l)) & 3;
        float val = (d == 0) ? ar : (d == 1) ? -ai : (d == 2) ? -ar : ai;
        int m = (((k >> 3) & 1) + ((l >> 3) & 1)) * 27 +
                (((k >> 2) & 1) + ((l >> 2) & 1)) * 9 +
                (((k >> 1) & 1) + ((l >> 1) & 1)) * 3 +
                ((k & 1) + (l & 1));
        atomicAdd(&Csh[m], val);
        __syncthreads();
        if (t < 81) g_Cpart[q][t * 8 + i] = Csh[t];

        // ---- Phase C: ticket; #63 sums partials into g_C and releases ----
        __threadfence();
        __syncthreads();
        if (t == 0) s_tick = atomicAdd(&g_ticket, 1);
        __syncthreads();
        if (s_tick == 63) {
            __threadfence();
            for (int idx = t; idx < 81 * 8; idx += 256) {
                float sum = 0.f;
#pragma unroll
                for (int qq = 0; qq < 8; ++qq) sum += __ldcg(&g_Cpart[qq][idx]);
                g_C[idx] = sum;
            }
            __syncthreads();
            if (t == 0) {
                g_ticket = 0;            // self-reset for graph replay
                asm volatile("st.release.gpu.global.u32 [%0], %1;"
                             :: "l"(&g_ready), "r"(1u) : "memory");
            }
        }
    }

    // ================= contraction (all 512 blocks) =================
    // Preamble BEFORE the spin: overlaps setup latency for consumer blocks.
    int gt = bid * 256 + t;
    int s = gt >> 1;                     // sample
    int half = gt & 1;                   // output half (0-3 / 4-7)
    const float QP = 0.78539816339744831f;  // pi/4

    float4 xv = __ldg(reinterpret_cast<const float4*>(x) + s);
    float c0, s_0, c1, s_1, c2, s_2, c3, s_3;
    __sincosf((xv.x + 1.f) * QP, &s_0, &c0);
    __sincosf((xv.y + 1.f) * QP, &s_1, &c1);
    __sincosf((xv.z + 1.f) * QP, &s_2, &c2);
    __sincosf((xv.w + 1.f) * QP, &s_3, &c3);
    float u0[3] = {c0 * c0, c0 * s_0, s_0 * s_0};
    float u1[3] = {c1 * c1, c1 * s_1, s_1 * s_1};
    float u2[3] = {c2 * c2, c2 * s_2, s_2 * s_2};
    float u3[3] = {c3 * c3, c3 * s_3, s_3 * s_3};

    ull u01d[9], u23d[9];
#pragma unroll
    for (int a = 0; a < 3; ++a)
#pragma unroll
        for (int c = 0; c < 3; ++c) {
            u01d[a * 3 + c] = dup2(u0[a] * u1[c]);
            u23d[a * 3 + c] = dup2(u2[a] * u3[c]);
        }

    // wait for C (acquire)
    if (t == 0) {
        unsigned v;
        do {
            asm volatile("ld.acquire.gpu.global.u32 %0, [%1];"
                         : "=r"(v) : "l"(&g_ready));
        } while (v == 0);
    }
    __syncthreads();

    // stage C into smem (aliases Ms; setup blocks are past their last Ms use)
    for (int idx = t; idx < 81 * 8; idx += 256)
        Cs[idx] = __ldcg(&g_C[idx]);
    __syncthreads();

    const float* Cb = Cs + half * 4;     // fold half-offset once

    ull acc0 = 0ull, acc1 = 0ull;
#pragma unroll
    for (int a = 0; a < 9; ++a) {
#pragma unroll
        for (int c = 0; c < 9; ++c) {
            const ull* cp = reinterpret_cast<const ull*>(Cb + (a * 9 + c) * 8);
            ull pp = mul2(u01d[a], u23d[c]);
            ffma2(acc0, cp[0], pp);
            ffma2(acc1, cp[1], pp);
        }
    }

    float2 p0 = *reinterpret_cast<float2*>(&acc0);
    float2 p1 = *reinterpret_cast<float2*>(&acc1);
    reinterpret_cast<float4*>(out + (size_t)s * 8)[half] =
        make_float4(p0.x, p0.y, p1.x, p1.y);

    // exit protocol: last block resets flags for the next graph replay
    if (t == 0) {
        unsigned prev = atomicAdd(&g_fin, 1);
        if (prev == NBLK - 1) {
            g_fin = 0;
            g_ready = 0;
            __threadfence();
        }
    }
}

// ---------------------------------------------------------------------------
extern "C" void kernel_launch(void* const* d_in, const int* in_sizes, int n_in,
                              void* d_out, int out_size) {
    const float* x = (const float*)d_in[0];        // (65536, 4)
    const float* params = (const float*)d_in[1];   // (2, 8, 3)
    float* out = (float*)d_out;                    // (65536, 8)

    fused_one<<<NBLK, 256>>>(x, params, out);
}